// round 12
// baseline (speedup 1.0000x reference)
#include <cuda_runtime.h>

// WarpDTI fused single-kernel, channel-planar gathers (z-contiguous, warp
// coalesced). R12: occupancy raised via __launch_bounds__(256,6) (~42 regs,
// 48 warps/SM) to hide gather latency; z-gradient via warp shuffles (z is
// lane-contiguous) with predicated edge loads; polar = 2 scaled + 3 plain
// Newton iterations (error floor is fp32 rounding, reached by iter ~5).

constexpr int HWD = 64 * 64 * 64;   // 262144 = 2^18

__global__ __launch_bounds__(256, 6)
void warp_dti_kernel(const float* __restrict__ dti,
                     const float* __restrict__ ddf,
                     float* __restrict__ out,
                     int total)
{
    int idx = blockIdx.x * blockDim.x + threadIdx.x;
    if (idx >= total) return;

    int vox = idx & (HWD - 1);
    int b   = idx >> 18;
    int z   =  vox        & 63;
    int y   = (vox >> 6)  & 63;
    int x   =  vox >> 12;
    unsigned lane = threadIdx.x & 31;

    const float* u = ddf + (size_t)b * 3 * HWD;

    float u0 = __ldg(u +           vox);
    float u1 = __ldg(u +     HWD + vox);
    float u2 = __ldg(u + 2 * HWD + vox);

    // ---------- Jacobian J = I + du_i/dx_j (jnp.gradient semantics) --------
    float J00, J01, J02, J10, J11, J12, J20, J21, J22;
    {   // axis 0 (x), stride 4096
        int ip = (x < 63) ? x + 1 : 63;
        int im = (x > 0 ) ? x - 1 : 0;
        float s = (ip - im == 2) ? 0.5f : 1.0f;
        int op = (ip - x) << 12, om = (im - x) << 12;
        J00 = (__ldg(u +           vox + op) - __ldg(u +           vox + om)) * s;
        J10 = (__ldg(u + HWD     + vox + op) - __ldg(u + HWD     + vox + om)) * s;
        J20 = (__ldg(u + 2 * HWD + vox + op) - __ldg(u + 2 * HWD + vox + om)) * s;
    }
    {   // axis 1 (y), stride 64
        int ip = (y < 63) ? y + 1 : 63;
        int im = (y > 0 ) ? y - 1 : 0;
        float s = (ip - im == 2) ? 0.5f : 1.0f;
        int op = (ip - y) << 6, om = (im - y) << 6;
        J01 = (__ldg(u +           vox + op) - __ldg(u +           vox + om)) * s;
        J11 = (__ldg(u + HWD     + vox + op) - __ldg(u + HWD     + vox + om)) * s;
        J21 = (__ldg(u + 2 * HWD + vox + op) - __ldg(u + 2 * HWD + vox + om)) * s;
    }
    {   // axis 2 (z), stride 1: neighbor values live in adjacent lanes.
        // Warp spans 32 consecutive z, so only lane 31 (z+1) and lane 0 (z-1)
        // need explicit loads; z==63 / z==0 boundaries coincide with those lanes.
        float a0 = __shfl_down_sync(0xFFFFFFFFu, u0, 1);
        float a1 = __shfl_down_sync(0xFFFFFFFFu, u1, 1);
        float a2 = __shfl_down_sync(0xFFFFFFFFu, u2, 1);
        float b0 = __shfl_up_sync  (0xFFFFFFFFu, u0, 1);
        float b1 = __shfl_up_sync  (0xFFFFFFFFu, u1, 1);
        float b2 = __shfl_up_sync  (0xFFFFFFFFu, u2, 1);
        if (lane == 31) {
            int op = (z < 63) ? 1 : 0;
            a0 = __ldg(u +           vox + op);
            a1 = __ldg(u + HWD     + vox + op);
            a2 = __ldg(u + 2 * HWD + vox + op);
        }
        if (lane == 0) {
            int om = (z > 0) ? -1 : 0;
            b0 = __ldg(u +           vox + om);
            b1 = __ldg(u + HWD     + vox + om);
            b2 = __ldg(u + 2 * HWD + vox + om);
        }
        float s = (z > 0 && z < 63) ? 0.5f : 1.0f;
        J02 = (a0 - b0) * s;
        J12 = (a1 - b1) * s;
        J22 = (a2 - b2) * s;
    }
    J00 += 1.0f; J11 += 1.0f; J22 += 1.0f;

    // ---------- trilinear warp (border clamp, align_corners) ----------
    float cx = fminf(fmaxf(u0 + (float)x, 0.0f), 63.0f);
    float cy = fminf(fmaxf(u1 + (float)y, 0.0f), 63.0f);
    float cz = fminf(fmaxf(u2 + (float)z, 0.0f), 63.0f);
    float xf = floorf(cx), yf = floorf(cy), zf = floorf(cz);
    float fx = cx - xf,   fy = cy - yf,   fz = cz - zf;
    int x0 = (int)xf, y0 = (int)yf, z0 = (int)zf;
    int x1 = min(x0 + 1, 63), y1 = min(y0 + 1, 63), z1 = min(z0 + 1, 63);

    int b00 = ((x0 << 6) + y0) << 6;
    int b01 = ((x0 << 6) + y1) << 6;
    int b10 = ((x1 << 6) + y0) << 6;
    int b11 = ((x1 << 6) + y1) << 6;

    float wx0 = 1.0f - fx, wy0 = 1.0f - fy, wz0 = 1.0f - fz;
    float w000 = wx0 * wy0 * wz0, w001 = wx0 * wy0 * fz;
    float w010 = wx0 * fy  * wz0, w011 = wx0 * fy  * fz;
    float w100 = fx  * wy0 * wz0, w101 = fx  * wy0 * fz;
    float w110 = fx  * fy  * wz0, w111 = fx  * fy  * fz;

    float m[6];
    const float* img = dti + (size_t)b * 6 * HWD;
    #pragma unroll
    for (int c = 0; c < 6; c++) {
        const float* p = img + (size_t)c * HWD;
        m[c] = w000 * __ldg(p + b00 + z0) + w001 * __ldg(p + b00 + z1)
             + w010 * __ldg(p + b01 + z0) + w011 * __ldg(p + b01 + z1)
             + w100 * __ldg(p + b10 + z0) + w101 * __ldg(p + b10 + z1)
             + w110 * __ldg(p + b11 + z0) + w111 * __ldg(p + b11 + z1);
    }

    // ---------- polar factor R = U V^T ----------
    float X00 = J00, X01 = J01, X02 = J02;
    float X10 = J10, X11 = J11, X12 = J12;
    float X20 = J20, X21 = J21, X22 = J22;

    // 2 scaled Newton iterations (Frobenius mu, fast-math — self-correcting)
    #pragma unroll
    for (int it = 0; it < 2; ++it) {
        float C00 = X11 * X22 - X12 * X21;
        float C01 = X12 * X20 - X10 * X22;
        float C02 = X10 * X21 - X11 * X20;
        float C10 = X21 * X02 - X22 * X01;
        float C11 = X22 * X00 - X20 * X02;
        float C12 = X20 * X01 - X21 * X00;
        float C20 = X01 * X12 - X02 * X11;
        float C21 = X02 * X10 - X00 * X12;
        float C22 = X00 * X11 - X01 * X10;
        float det = X00 * C00 + X01 * C01 + X02 * C02;
        float adet = fmaxf(fabsf(det), 1e-12f);
        float sdet = (det < 0.0f) ? -adet : adet;
        float nX = X00*X00 + X01*X01 + X02*X02 + X10*X10 + X11*X11 + X12*X12
                 + X20*X20 + X21*X21 + X22*X22;
        float nC = C00*C00 + C01*C01 + C02*C02 + C10*C10 + C11*C11 + C12*C12
                 + C20*C20 + C21*C21 + C22*C22;
        float mu = exp2f(0.25f * __log2f(nC / nX)) * rsqrtf(adet);
        mu = fminf(fmaxf(mu, 1e-4f), 1e4f);
        float a = 0.5f * mu;
        float c = __fdividef(0.5f, mu * sdet);
        X00 = a * X00 + c * C00; X01 = a * X01 + c * C01; X02 = a * X02 + c * C02;
        X10 = a * X10 + c * C10; X11 = a * X11 + c * C11; X12 = a * X12 + c * C12;
        X20 = a * X20 + c * C20; X21 = a * X21 + c * C21; X22 = a * X22 + c * C22;
    }
    // 3 plain Newton iterations: X <- 0.5*(X + cof(X)/det)
    #pragma unroll
    for (int it = 0; it < 3; ++it) {
        float C00 = X11 * X22 - X12 * X21;
        float C01 = X12 * X20 - X10 * X22;
        float C02 = X10 * X21 - X11 * X20;
        float C10 = X21 * X02 - X22 * X01;
        float C11 = X22 * X00 - X20 * X02;
        float C12 = X20 * X01 - X21 * X00;
        float C20 = X01 * X12 - X02 * X11;
        float C21 = X02 * X10 - X00 * X12;
        float C22 = X00 * X11 - X01 * X10;
        float det = X00 * C00 + X01 * C01 + X02 * C02;
        float adet = fmaxf(fabsf(det), 1e-12f);
        float sdet = (det < 0.0f) ? -adet : adet;
        float c = __fdividef(0.5f, sdet);
        X00 = 0.5f * X00 + c * C00; X01 = 0.5f * X01 + c * C01; X02 = 0.5f * X02 + c * C02;
        X10 = 0.5f * X10 + c * C10; X11 = 0.5f * X11 + c * C11; X12 = 0.5f * X12 + c * C12;
        X20 = 0.5f * X20 + c * C20; X21 = 0.5f * X21 + c * C21; X22 = 0.5f * X22 + c * C22;
    }

    // ---------- S = R^T M R, lower triangle ----------
    float w0x = m[0]*X00 + m[1]*X10 + m[3]*X20;
    float w0y = m[1]*X00 + m[2]*X10 + m[4]*X20;
    float w0z = m[3]*X00 + m[4]*X10 + m[5]*X20;
    float w1x = m[0]*X01 + m[1]*X11 + m[3]*X21;
    float w1y = m[1]*X01 + m[2]*X11 + m[4]*X21;
    float w1z = m[3]*X01 + m[4]*X11 + m[5]*X21;
    float w2x = m[0]*X02 + m[1]*X12 + m[3]*X22;
    float w2y = m[1]*X02 + m[2]*X12 + m[4]*X22;
    float w2z = m[3]*X02 + m[4]*X12 + m[5]*X22;

    float S00 = X00*w0x + X10*w0y + X20*w0z;
    float S10 = X01*w0x + X11*w0y + X21*w0z;
    float S11 = X01*w1x + X11*w1y + X21*w1z;
    float S20 = X02*w0x + X12*w0y + X22*w0z;
    float S21 = X02*w1x + X12*w1y + X22*w1z;
    float S22 = X02*w2x + X12*w2y + X22*w2z;

    float* o = out + (size_t)b * 6 * HWD + vox;
    o[0]       = S00;
    o[HWD]     = S10;
    o[2 * HWD] = S11;
    o[3 * HWD] = S20;
    o[4 * HWD] = S21;
    o[5 * HWD] = S22;
}

extern "C" void kernel_launch(void* const* d_in, const int* in_sizes, int n_in,
                              void* d_out, int out_size)
{
    const float* dti = (const float*)d_in[0];
    const float* ddf = (const float*)d_in[1];
    int s0 = in_sizes[0], s1 = in_sizes[1];
    if (s0 < s1) { const float* t = dti; dti = ddf; ddf = t; int ts = s0; s0 = s1; s1 = ts; }
    int B = s1 / (3 * HWD);
    int total = B * HWD;
    int threads = 256;
    int blocks = (total + threads - 1) / threads;
    warp_dti_kernel<<<blocks, threads>>>(dti, ddf, (float*)d_out, total);
}